// round 2
// baseline (speedup 1.0000x reference)
#include <cuda_runtime.h>
#include <cstdint>
#include <cstddef>

// ---------------------------------------------------------------------------
// Neural CDE classifier as ONE persistent clustered kernel.
// grid = 128 CTAs = 16 clusters x 8, 256 thr/CTA, 1 CTA/SM (smem-bound).
// Each cluster integrates 32 batch elements through 2047 RK4 steps on-chip.
// vf_W2 (2048x128) row-sliced across the 8 cluster CTAs (SMEM-resident).
// Per RK4 substep: h0 slice -> allgather -> h1 slice -> allgather ->
// W2-slice GEMM + tanh + dx-contraction -> k allgather. dt cancels exactly.
// ---------------------------------------------------------------------------

namespace {
constexpr int NSTEPS = 2047;

// shared memory layout (float offsets)
constexpr int OFF_W2T = 0;        // [128][256] vf_W2 slice, k-major
constexpr int OFF_W1T = 32768;    // [128][16]  vf_W1 slice, k-major, row-paired
constexpr int OFF_W0T = 34816;    // [64][16]   vf_W0 slice, k-major, row-paired
constexpr int OFF_B0  = 35840;    // [16]
constexpr int OFF_B1  = 35856;    // [16]
constexpr int OFF_B2  = 35872;    // [256]
constexpr int OFF_Y   = 36128;    // [64][32]
constexpr int OFF_YIN = 38176;    // [64][32]
constexpr int OFF_KC  = 40224;    // [64][32]
constexpr int OFF_KS  = 42272;    // [64][32]
constexpr int OFF_H0  = 44320;    // [128][32]
constexpr int OFF_H1  = 48416;    // [128][32]
constexpr int OFF_DXS = 52512;    // [32][32]  dx, d-major
constexpr int OFF_XSC = 53536;    // [32][32]  xs at current t, d-major
constexpr int SMEM_FLOATS = 54560;
constexpr int SMEM_BYTES  = SMEM_FLOATS * 4;   // 218240 B
}

__device__ __forceinline__ uint32_t s2u(const void* p) {
    return (uint32_t)__cvta_generic_to_shared(p);
}

__device__ __forceinline__ void st_remote(uint32_t laddr, int rank, float v) {
    uint32_t raddr;
    asm volatile("mapa.shared::cluster.u32 %0, %1, %2;" : "=r"(raddr) : "r"(laddr), "r"(rank));
    asm volatile("st.shared::cluster.f32 [%0], %1;" :: "r"(raddr), "f"(v) : "memory");
}

__device__ __forceinline__ void cluster_sync_() {
    asm volatile("barrier.cluster.arrive.aligned;" ::: "memory");
    asm volatile("barrier.cluster.wait.aligned;" ::: "memory");
}

__device__ __forceinline__ float tanh_f(float x) {
    float ax = fabsf(x);
    float e  = __expf(-2.0f * ax);
    float r  = __fdividef(1.0f - e, 1.0f + e);
    return copysignf(r, x);
}

__device__ __forceinline__ float gelu_f(float x) {
    // JAX default gelu (tanh approximation)
    float x3 = x * x * x;
    float t  = tanh_f(0.7978845608028654f * fmaf(0.044715f, x3, x));
    return 0.5f * x * (1.0f + t);
}

__global__ void __launch_bounds__(256, 1)
ncde_kernel(const float* __restrict__ xs,
            const float* __restrict__ eW0, const float* __restrict__ eb0,
            const float* __restrict__ eW1, const float* __restrict__ eb1,
            const float* __restrict__ eW2, const float* __restrict__ eb2,
            const float* __restrict__ vW0, const float* __restrict__ vb0,
            const float* __restrict__ vW1, const float* __restrict__ vb1,
            const float* __restrict__ vW2, const float* __restrict__ vb2,
            const float* __restrict__ dW,  const float* __restrict__ db,
            float* __restrict__ out)
{
    extern __shared__ float sm[];
    const int tid   = threadIdx.x;
    const int rank  = blockIdx.x & 7;    // CTA rank within cluster
    const int cid   = blockIdx.x >> 3;   // cluster id (16)
    const int bbase = cid * 32;          // first batch element of this cluster

    float* sW2T = sm + OFF_W2T;
    float* sW1T = sm + OFF_W1T;
    float* sW0T = sm + OFF_W0T;
    float* sB0  = sm + OFF_B0;
    float* sB1  = sm + OFF_B1;
    float* sB2  = sm + OFF_B2;
    float* sY   = sm + OFF_Y;
    float* sYIN = sm + OFF_YIN;
    float* sKC  = sm + OFF_KC;
    float* sKS  = sm + OFF_KS;
    float* sH0  = sm + OFF_H0;
    float* sH1  = sm + OFF_H1;
    float* sDX  = sm + OFF_DXS;
    float* sXC  = sm + OFF_XSC;

    // per-thread xs mapping: thread owns (b = tid>>3, d = (tid&7)*4 .. +3)
    const int xb  = tid >> 3;
    const int xdq = tid & 7;
    const float* xsrow = xs + (size_t)(bbase + xb) * 2048 * 32 + xdq * 4;

    // ---- stage xs[:, 0] into xs_cur (d-major [32][32]) ----
    {
        float4 v = *reinterpret_cast<const float4*>(xsrow);
        sXC[(xdq * 4 + 0) * 32 + xb] = v.x;
        sXC[(xdq * 4 + 1) * 32 + xb] = v.y;
        sXC[(xdq * 4 + 2) * 32 + xb] = v.z;
        sXC[(xdq * 4 + 3) * 32 + xb] = v.w;
    }

    // ---- encoder weights transposed into W2T scratch area ----
    float* sE0 = sW2T;          // [32][128]
    float* sE1 = sW2T + 4096;   // [128][128]
    float* sE2 = sW2T + 20480;  // [128][64]
    for (int i = tid; i < 4096;  i += 256) { int r = i & 127, kk = i >> 7; sE0[i] = eW0[r * 32  + kk]; }
    for (int i = tid; i < 16384; i += 256) { int r = i & 127, kk = i >> 7; sE1[i] = eW1[r * 128 + kk]; }
    for (int i = tid; i < 8192;  i += 256) { int r = i & 63,  kk = i >> 6; sE2[i] = eW2[r * 128 + kk]; }
    __syncthreads();

    // ---- encoder: y0 = enc(xs[:,0]) (replicated in every CTA) ----
    {
        int b = tid & 31, rbase = (tid >> 5) * 16;
        float acc[16];
        #pragma unroll
        for (int j = 0; j < 16; ++j) acc[j] = eb0[rbase + j];
        for (int kk = 0; kk < 32; ++kk) {
            float x = sXC[kk * 32 + b];
            #pragma unroll
            for (int j = 0; j < 16; ++j) acc[j] = fmaf(sE0[kk * 128 + rbase + j], x, acc[j]);
        }
        #pragma unroll
        for (int j = 0; j < 16; ++j) sH0[(rbase + j) * 32 + b] = fmaxf(acc[j], 0.0f);
    }
    __syncthreads();
    {
        int b = tid & 31, rbase = (tid >> 5) * 16;
        float acc[16];
        #pragma unroll
        for (int j = 0; j < 16; ++j) acc[j] = eb1[rbase + j];
        for (int kk = 0; kk < 128; ++kk) {
            float x = sH0[kk * 32 + b];
            #pragma unroll
            for (int j = 0; j < 16; ++j) acc[j] = fmaf(sE1[kk * 128 + rbase + j], x, acc[j]);
        }
        #pragma unroll
        for (int j = 0; j < 16; ++j) sH1[(rbase + j) * 32 + b] = fmaxf(acc[j], 0.0f);
    }
    __syncthreads();
    {
        int b = tid & 31, rbase = (tid >> 5) * 8;
        float acc[8];
        #pragma unroll
        for (int j = 0; j < 8; ++j) acc[j] = eb2[rbase + j];
        for (int kk = 0; kk < 128; ++kk) {
            float x = sH1[kk * 32 + b];
            #pragma unroll
            for (int j = 0; j < 8; ++j) acc[j] = fmaf(sE2[kk * 64 + rbase + j], x, acc[j]);
        }
        #pragma unroll
        for (int j = 0; j < 8; ++j) sY[(rbase + j) * 32 + b] = acc[j];
    }
    __syncthreads();

    // ---- load vf weight slices (overwrites encoder scratch) ----
    for (int i = tid; i < 32768; i += 256) {
        int rloc = i & 255, kk = i >> 8;
        sW2T[i] = vW2[(size_t)(rank * 256 + rloc) * 128 + kk];
    }
    for (int i = tid; i < 2048; i += 256) {
        int s_ = i & 15, kk = i >> 4;
        int rp = s_ >> 1, h = s_ & 1;
        sW1T[i] = vW1[(rank * 16 + rp + 8 * h) * 128 + kk];
    }
    for (int i = tid; i < 1024; i += 256) {
        int s_ = i & 15, kk = i >> 4;
        int rp = s_ >> 1, h = s_ & 1;
        sW0T[i] = vW0[(rank * 16 + rp + 8 * h) * 64 + kk];
    }
    if (tid < 16)                 sB0[tid]      = vb0[rank * 16 + tid];
    else if (tid < 32)            sB1[tid - 16] = vb1[rank * 16 + tid - 16];
    if (tid < 256)                sB2[tid]      = vb2[rank * 256 + tid];
    cluster_sync_();

    // ---- main RK4 scan ----
    for (int t = 0; t < NSTEPS; ++t) {
        // prefetch xs[:, t+1] early; consumed before B1 of substep 0
        float4 xn = *reinterpret_cast<const float4*>(xsrow + (size_t)(t + 1) * 32);

        #pragma unroll
        for (int s = 0; s < 4; ++s) {
            const float* yin = (s == 0) ? sY : sYIN;

            // ---- layer 0: h0 slice = gelu(W0s @ yin + b0s), push to all ranks
            {
                int b = tid & 31, rp = tid >> 5;
                float a0 = sB0[rp], a1 = sB0[rp + 8];
                #pragma unroll 8
                for (int kk = 0; kk < 64; ++kk) {
                    float  x = yin[kk * 32 + b];
                    float2 w = *reinterpret_cast<const float2*>(&sW0T[kk * 16 + rp * 2]);
                    a0 = fmaf(w.x, x, a0);
                    a1 = fmaf(w.y, x, a1);
                }
                a0 = gelu_f(a0);
                a1 = gelu_f(a1);
                uint32_t p0 = s2u(&sH0[(rank * 16 + rp) * 32 + b]);
                uint32_t p1 = s2u(&sH0[(rank * 16 + rp + 8) * 32 + b]);
                #pragma unroll
                for (int r = 0; r < 8; ++r) { st_remote(p0, r, a0); st_remote(p1, r, a1); }
            }

            if (s == 0) {
                // dx for this step; update xs_cur (thread-exclusive elements)
                float c0 = sXC[(xdq * 4 + 0) * 32 + xb];
                float c1 = sXC[(xdq * 4 + 1) * 32 + xb];
                float c2 = sXC[(xdq * 4 + 2) * 32 + xb];
                float c3 = sXC[(xdq * 4 + 3) * 32 + xb];
                sDX[(xdq * 4 + 0) * 32 + xb] = xn.x - c0;
                sDX[(xdq * 4 + 1) * 32 + xb] = xn.y - c1;
                sDX[(xdq * 4 + 2) * 32 + xb] = xn.z - c2;
                sDX[(xdq * 4 + 3) * 32 + xb] = xn.w - c3;
                sXC[(xdq * 4 + 0) * 32 + xb] = xn.x;
                sXC[(xdq * 4 + 1) * 32 + xb] = xn.y;
                sXC[(xdq * 4 + 2) * 32 + xb] = xn.z;
                sXC[(xdq * 4 + 3) * 32 + xb] = xn.w;
            }
            cluster_sync_();  // B1: h0 complete everywhere

            // ---- layer 1: h1 slice = gelu(W1s @ h0 + b1s), push to all ranks
            {
                int b = tid & 31, rp = tid >> 5;
                float a0 = sB1[rp], a1 = sB1[rp + 8];
                #pragma unroll 8
                for (int kk = 0; kk < 128; ++kk) {
                    float  x = sH0[kk * 32 + b];
                    float2 w = *reinterpret_cast<const float2*>(&sW1T[kk * 16 + rp * 2]);
                    a0 = fmaf(w.x, x, a0);
                    a1 = fmaf(w.y, x, a1);
                }
                a0 = gelu_f(a0);
                a1 = gelu_f(a1);
                uint32_t p0 = s2u(&sH1[(rank * 16 + rp) * 32 + b]);
                uint32_t p1 = s2u(&sH1[(rank * 16 + rp + 8) * 32 + b]);
                #pragma unroll
                for (int r = 0; r < 8; ++r) { st_remote(p0, r, a0); st_remote(p1, r, a1); }
            }
            cluster_sync_();  // B2: h1 complete everywhere

            // ---- layer 2: u = tanh(W2s @ h1 + b2s); k slice = sum_d u*dx
            {
                int bq = tid & 7;          // b quad: b = bq*4 .. bq*4+3
                int rg = tid >> 3;         // row group: rows rg*8 .. rg*8+7 (local)
                float acc[8][4];
                #pragma unroll
                for (int j = 0; j < 8; ++j)
                    #pragma unroll
                    for (int i = 0; i < 4; ++i) acc[j][i] = 0.0f;

                #pragma unroll 4
                for (int kk = 0; kk < 128; ++kk) {
                    float4 x4 = *reinterpret_cast<const float4*>(&sH1[kk * 32 + bq * 4]);
                    float4 wA = *reinterpret_cast<const float4*>(&sW2T[kk * 256 + rg * 8]);
                    float4 wB = *reinterpret_cast<const float4*>(&sW2T[kk * 256 + rg * 8 + 4]);
                    float xv[4] = {x4.x, x4.y, x4.z, x4.w};
                    float wv[8] = {wA.x, wA.y, wA.z, wA.w, wB.x, wB.y, wB.z, wB.w};
                    #pragma unroll
                    for (int j = 0; j < 8; ++j)
                        #pragma unroll
                        for (int i = 0; i < 4; ++i)
                            acc[j][i] = fmaf(wv[j], xv[i], acc[j][i]);
                }

                float kp[4] = {0.0f, 0.0f, 0.0f, 0.0f};
                int dbase = (rg & 3) * 8;
                #pragma unroll
                for (int j = 0; j < 8; ++j) {
                    float  bias = sB2[rg * 8 + j];
                    float4 dx4  = *reinterpret_cast<const float4*>(&sDX[(dbase + j) * 32 + bq * 4]);
                    float u0 = tanh_f(acc[j][0] + bias);
                    float u1 = tanh_f(acc[j][1] + bias);
                    float u2 = tanh_f(acc[j][2] + bias);
                    float u3 = tanh_f(acc[j][3] + bias);
                    kp[0] = fmaf(u0, dx4.x, kp[0]);
                    kp[1] = fmaf(u1, dx4.y, kp[1]);
                    kp[2] = fmaf(u2, dx4.z, kp[2]);
                    kp[3] = fmaf(u3, dx4.w, kp[3]);
                }
                // reduce over the 4 d-groups (lanes xor 8, 16 within warp)
                #pragma unroll
                for (int i = 0; i < 4; ++i) {
                    kp[i] += __shfl_xor_sync(0xffffffffu, kp[i], 8);
                    kp[i] += __shfl_xor_sync(0xffffffffu, kp[i], 16);
                }
                if (((tid >> 3) & 3) == 0) {
                    int mloc = tid >> 5;
                    uint32_t p = s2u(&sKC[(rank * 8 + mloc) * 32 + bq * 4]);
                    #pragma unroll
                    for (int r = 0; r < 8; ++r) {
                        st_remote(p,      r, kp[0]);
                        st_remote(p + 4,  r, kp[1]);
                        st_remote(p + 8,  r, kp[2]);
                        st_remote(p + 12, r, kp[3]);
                    }
                }
            }
            cluster_sync_();  // B3: k complete everywhere

            // ---- RK4 combine (replicated local update) ----
            {
                const float w_s = (s == 1 || s == 2) ? 2.0f : 1.0f;
                int base = tid * 8;
                #pragma unroll
                for (int g = 0; g < 2; ++g) {
                    int f = base + g * 4;
                    float4 kc = *reinterpret_cast<float4*>(&sKC[f]);
                    float4 ks;
                    if (s == 0) {
                        ks = kc;
                    } else {
                        ks = *reinterpret_cast<float4*>(&sKS[f]);
                        ks.x = fmaf(w_s, kc.x, ks.x);
                        ks.y = fmaf(w_s, kc.y, ks.y);
                        ks.z = fmaf(w_s, kc.z, ks.z);
                        ks.w = fmaf(w_s, kc.w, ks.w);
                    }
                    *reinterpret_cast<float4*>(&sKS[f]) = ks;
                    float4 y4 = *reinterpret_cast<float4*>(&sY[f]);
                    if (s < 3) {
                        const float c = (s == 2) ? 1.0f : 0.5f;
                        float4 yi;
                        yi.x = fmaf(c, kc.x, y4.x);
                        yi.y = fmaf(c, kc.y, y4.y);
                        yi.z = fmaf(c, kc.z, y4.z);
                        yi.w = fmaf(c, kc.w, y4.w);
                        *reinterpret_cast<float4*>(&sYIN[f]) = yi;
                    } else {
                        const float sixth = 1.0f / 6.0f;
                        y4.x = fmaf(sixth, ks.x, y4.x);
                        y4.y = fmaf(sixth, ks.y, y4.y);
                        y4.z = fmaf(sixth, ks.z, y4.z);
                        y4.w = fmaf(sixth, ks.w, y4.w);
                        *reinterpret_cast<float4*>(&sY[f]) = y4;
                    }
                }
            }
            __syncthreads();
        }
    }

    // ---- decoder + sigmoid (rank 0 CTA of each cluster) ----
    if (rank == 0 && tid < 32) {
        float acc = db[0];
        #pragma unroll 8
        for (int r = 0; r < 64; ++r) acc = fmaf(dW[r], sY[r * 32 + tid], acc);
        out[bbase + tid] = __fdividef(1.0f, 1.0f + __expf(-acc));
    }
}

extern "C" void kernel_launch(void* const* d_in, const int* in_sizes, int n_in,
                              void* d_out, int out_size) {
    (void)in_sizes; (void)n_in; (void)out_size;
    const float* xs  = (const float*)d_in[1];
    const float* eW0 = (const float*)d_in[2];
    const float* eb0 = (const float*)d_in[3];
    const float* eW1 = (const float*)d_in[4];
    const float* eb1 = (const float*)d_in[5];
    const float* eW2 = (const float*)d_in[6];
    const float* eb2 = (const float*)d_in[7];
    const float* vW0 = (const float*)d_in[8];
    const float* vb0 = (const float*)d_in[9];
    const float* vW1 = (const float*)d_in[10];
    const float* vb1 = (const float*)d_in[11];
    const float* vW2 = (const float*)d_in[12];
    const float* vb2 = (const float*)d_in[13];
    const float* dW  = (const float*)d_in[14];
    const float* db  = (const float*)d_in[15];
    float* out = (float*)d_out;

    cudaFuncSetAttribute(ncde_kernel, cudaFuncAttributeMaxDynamicSharedMemorySize, SMEM_BYTES);

    cudaLaunchConfig_t cfg = {};
    cfg.gridDim  = dim3(128, 1, 1);
    cfg.blockDim = dim3(256, 1, 1);
    cfg.dynamicSmemBytes = SMEM_BYTES;
    cfg.stream = 0;
    cudaLaunchAttribute attrs[1];
    attrs[0].id = cudaLaunchAttributeClusterDimension;
    attrs[0].val.clusterDim.x = 8;
    attrs[0].val.clusterDim.y = 1;
    attrs[0].val.clusterDim.z = 1;
    cfg.attrs = attrs;
    cfg.numAttrs = 1;

    cudaLaunchKernelEx(&cfg, ncde_kernel,
                       xs, eW0, eb0, eW1, eb1, eW2, eb2,
                       vW0, vb0, vW1, vb1, vW2, vb2, dW, db, out);
}